// round 1
// baseline (speedup 1.0000x reference)
#include <cuda_runtime.h>
#include <cuda_bf16.h>
#include <math.h>

// Problem constants
#define BB    16
#define NP1   65
#define TOK   (BB*NP1)      // 1040
#define MM    256
#define DD    512
#define HH    8
#define DH    64
#define LL    3
#define DFF   2048

// ---------------- scratch (device globals; no allocation allowed) ----------
__device__ float g_xs  [TOK*DD];
__device__ float g_qkv [TOK*3*DD];
__device__ float g_attn[TOK*DD];
__device__ float g_tmp [TOK*DD];
__device__ float g_ff  [TOK*DFF];
__device__ float g_hraw[TOK*MM];

// ---------------- embed: conv-collapse + fc + LN + GELU + pos --------------
__global__ __launch_bounds__(256)
void embed_kernel(const float* __restrict__ marg, const float* __restrict__ conv_w,
                  const float* __restrict__ conv_b, const float* __restrict__ fc_w,
                  const float* __restrict__ fc_b, const float* __restrict__ ln_g,
                  const float* __restrict__ ln_b, const float* __restrict__ pos,
                  float* __restrict__ xs)
{
    int row = blockIdx.x;      // 0..1039
    int tid = threadIdx.x;     // 256 threads
    __shared__ float red[256];
    __shared__ float e[128];

    const float* x = marg + (size_t)row * MM;
    float v = x[tid];
    red[tid] = v;
    __syncthreads();
    for (int s = 128; s > 0; s >>= 1) { if (tid < s) red[tid] += red[tid+s]; __syncthreads(); }
    float S = red[0];
    __syncthreads();

    if (tid < 128) {
        float x0 = x[0], x1 = x[1], xm2 = x[MM-2], xm1 = x[MM-1];
        const float* w = conv_w + tid*5;
        // mean over spatial of padded conv == weighted combination of edge-corrected sums
        float acc = w[0]*(S - xm2 - xm1) + w[1]*(S - xm1) + w[2]*S
                  + w[3]*(S - x0)        + w[4]*(S - x0 - x1);
        e[tid] = conv_b[tid] + acc * (1.0f/(float)MM);
    }
    __syncthreads();

    // fc: each thread two output dims (tid, tid+256)
    float t0 = fc_b[tid], t1 = fc_b[tid+256];
    #pragma unroll 4
    for (int c = 0; c < 128; c++) {
        float ec = e[c];
        t0 += ec * fc_w[c*DD + tid];
        t1 += ec * fc_w[c*DD + tid + 256];
    }

    // LayerNorm over 512
    red[tid] = t0 + t1; __syncthreads();
    for (int s = 128; s > 0; s >>= 1) { if (tid < s) red[tid] += red[tid+s]; __syncthreads(); }
    float mean = red[0] * (1.0f/(float)DD);
    __syncthreads();
    float d0 = t0 - mean, d1 = t1 - mean;
    red[tid] = d0*d0 + d1*d1; __syncthreads();
    for (int s = 128; s > 0; s >>= 1) { if (tid < s) red[tid] += red[tid+s]; __syncthreads(); }
    float inv = rsqrtf(red[0] * (1.0f/(float)DD) + 1e-5f);

    float y0 = d0*inv*ln_g[tid]     + ln_b[tid];
    float y1 = d1*inv*ln_g[tid+256] + ln_b[tid+256];
    // exact GELU
    y0 = 0.5f*y0*(1.0f + erff(y0*0.70710678118654752f));
    y1 = 0.5f*y1*(1.0f + erff(y1*0.70710678118654752f));

    int p = row % NP1;
    xs[(size_t)row*DD + tid]       = y0 + pos[p*DD + tid];
    xs[(size_t)row*DD + tid + 256] = y1 + pos[p*DD + tid + 256];
}

// ---------------- generic GEMM: C[m,n] = sum_k A[m,k]*W[n,k] + bias[n] -----
// EPI: 0 = none, 1 = exact GELU
#define GT   64   // tile
#define GKS  16   // k-step

template<int EPI>
__global__ __launch_bounds__(256)
void gemm_bias(const float* __restrict__ A, const float* __restrict__ W,
               const float* __restrict__ bias, float* __restrict__ C,
               int M, int N, int K)
{
    __shared__ float As[GKS][GT+4];
    __shared__ float Ws[GKS][GT+4];

    int tid = threadIdx.x;
    int tx = tid & 15, ty = tid >> 4;
    int lk = tid & (GKS-1);          // 0..15
    int lm = tid >> 4;               // 0..15
    int m0 = blockIdx.y * GT, n0 = blockIdx.x * GT;

    float acc[4][4];
    #pragma unroll
    for (int i = 0; i < 4; i++)
        #pragma unroll
        for (int j = 0; j < 4; j++) acc[i][j] = 0.f;

    for (int k0 = 0; k0 < K; k0 += GKS) {
        #pragma unroll
        for (int i = 0; i < 4; i++) {
            int m = m0 + lm + 16*i;
            As[lk][lm + 16*i] = (m < M) ? A[(size_t)m*K + k0 + lk] : 0.f;
            int n = n0 + lm + 16*i;
            Ws[lk][lm + 16*i] = (n < N) ? W[(size_t)n*K + k0 + lk] : 0.f;
        }
        __syncthreads();
        #pragma unroll
        for (int kk = 0; kk < GKS; kk++) {
            float a[4], w[4];
            #pragma unroll
            for (int i = 0; i < 4; i++) a[i] = As[kk][ty*4 + i];
            #pragma unroll
            for (int j = 0; j < 4; j++) w[j] = Ws[kk][tx*4 + j];
            #pragma unroll
            for (int i = 0; i < 4; i++)
                #pragma unroll
                for (int j = 0; j < 4; j++)
                    acc[i][j] = fmaf(a[i], w[j], acc[i][j]);
        }
        __syncthreads();
    }

    #pragma unroll
    for (int i = 0; i < 4; i++) {
        int m = m0 + ty*4 + i;
        if (m >= M) continue;
        #pragma unroll
        for (int j = 0; j < 4; j++) {
            int n = n0 + tx*4 + j;
            if (n >= N) continue;
            float val = acc[i][j] + bias[n];
            if (EPI == 1)
                val = 0.5f*val*(1.0f + erff(val*0.70710678118654752f));
            C[(size_t)m*N + n] = val;
        }
    }
}

// ---------------- attention: one block per (b,h) ---------------------------
__global__ __launch_bounds__(256)
void attn_kernel(const float* __restrict__ qkv, float* __restrict__ attn)
{
    int bh = blockIdx.x;
    int b = bh >> 3, h = bh & 7;
    __shared__ float Ks[NP1][65];   // pitch 65: conflict-free row reads across lanes
    __shared__ float Vs[NP1][64];
    __shared__ float Ps[8][72];

    int tid = threadIdx.x, lane = tid & 31, w = tid >> 5;

    for (int idx = tid; idx < NP1*64; idx += 256) {
        int j = idx >> 6, k = idx & 63;
        size_t base = ((size_t)(b*NP1 + j))*(3*DD) + h*DH + k;
        Ks[j][k] = qkv[base + DD];
        Vs[j][k] = qkv[base + 2*DD];
    }
    __syncthreads();

    const float scale = 0.125f;  // 1/sqrt(64)

    for (int qi = w; qi < NP1; qi += 8) {
        size_t qbase = ((size_t)(b*NP1 + qi))*(3*DD) + h*DH;
        float2 qp = *(const float2*)(qkv + qbase + 2*lane);
        float qa = qp.x, qb = qp.y;

        float s0 = 0.f, s1 = 0.f, s2 = 0.f;
        #pragma unroll
        for (int k = 0; k < 64; k++) {
            float qv = __shfl_sync(0xffffffffu, (k & 1) ? qb : qa, k >> 1);
            s0 = fmaf(qv, Ks[lane][k],      s0);
            s1 = fmaf(qv, Ks[lane + 32][k], s1);
            s2 = fmaf(qv, Ks[64][k],        s2);   // j=64 (broadcast; identical in all lanes)
        }
        s0 *= scale; s1 *= scale; s2 *= scale;

        float mx = fmaxf(fmaxf(s0, s1), s2);
        #pragma unroll
        for (int o = 16; o > 0; o >>= 1) mx = fmaxf(mx, __shfl_xor_sync(0xffffffffu, mx, o));

        float e0 = expf(s0 - mx), e1 = expf(s1 - mx), e2 = expf(s2 - mx);
        float ls = e0 + e1;
        #pragma unroll
        for (int o = 16; o > 0; o >>= 1) ls += __shfl_xor_sync(0xffffffffu, ls, o);
        float total = ls + e2;            // e2 identical in all lanes: count once
        float rinv = 1.0f / total;

        Ps[w][lane]      = e0 * rinv;
        Ps[w][lane + 32] = e1 * rinv;
        if (lane == 0) Ps[w][64] = e2 * rinv;
        __syncwarp();

        float o0 = 0.f, o1 = 0.f;
        #pragma unroll 5
        for (int j = 0; j < NP1; j++) {
            float pj = Ps[w][j];
            o0 = fmaf(pj, Vs[j][lane],      o0);
            o1 = fmaf(pj, Vs[j][lane + 32], o1);
        }
        size_t obase = ((size_t)(b*NP1 + qi))*DD + h*DH;
        attn[obase + lane]      = o0;
        attn[obase + lane + 32] = o1;
        __syncwarp();
    }
}

// ---------------- residual + LayerNorm (in place on xs) --------------------
__global__ __launch_bounds__(256)
void ln_res_kernel(const float* __restrict__ add, const float* __restrict__ g,
                   const float* __restrict__ bta, float* __restrict__ xs)
{
    int row = blockIdx.x, tid = threadIdx.x;
    __shared__ float red[256];
    size_t base = (size_t)row*DD;
    float v0 = xs[base + tid]       + add[base + tid];
    float v1 = xs[base + tid + 256] + add[base + tid + 256];

    red[tid] = v0 + v1; __syncthreads();
    for (int s = 128; s > 0; s >>= 1) { if (tid < s) red[tid] += red[tid+s]; __syncthreads(); }
    float mean = red[0] * (1.0f/(float)DD);
    __syncthreads();
    float d0 = v0 - mean, d1 = v1 - mean;
    red[tid] = d0*d0 + d1*d1; __syncthreads();
    for (int s = 128; s > 0; s >>= 1) { if (tid < s) red[tid] += red[tid+s]; __syncthreads(); }
    float inv = rsqrtf(red[0] * (1.0f/(float)DD) + 1e-5f);

    xs[base + tid]       = d0*inv*g[tid]       + bta[tid];
    xs[base + tid + 256] = d1*inv*g[tid + 256] + bta[tid + 256];
}

// ---------------- MMOT tail: closed-form truncated-geometric softmax -------
// logits over j are linear in j  ->  P_j ∝ q^j,  q = exp(-|t|), symmetry flip for t<0.
// S0 = sum q^j, S1 = sum j q^j over j=0..255 built by 8 cancellation-free doublings.
__global__ __launch_bounds__(256)
void tail_kernel(const float* __restrict__ hraw, const float* __restrict__ marg,
                 const float* __restrict__ xg, float* __restrict__ hout)
{
    int blk = blockIdx.x;          // 0..1023
    int b = blk >> 6, n = blk & 63;
    int tid = threadIdx.x;         // 256
    int tok = b*NP1 + n;

    float hr = hraw[(size_t)tok*MM + tid];
    const float DELTA = 6.0f/255.0f;
    float t = hr * (DELTA / 0.01f);
    float tt = fabsf(t);
    float q = expf(-tt);

    float S0 = 1.f, S1 = 0.f, p = q, mcnt = 1.f;
    #pragma unroll
    for (int it = 0; it < 8; it++) {   // 2^8 = 256 terms
        S1 = S1 + p*(S1 + mcnt*S0);
        S0 = S0 + p*S0;
        p  = p*p;
        mcnt *= 2.f;
    }
    float f = S1 / S0;
    if (t < 0.f) f = 255.f - f;

    float expected = -3.f + DELTA * f;
    float drift = expected - xg[tid];
    float mu = marg[(size_t)tok*MM + tid];

    __shared__ float r1[256], r2[256];
    r1[tid] = mu * drift; r2[tid] = mu;
    __syncthreads();
    for (int s = 128; s > 0; s >>= 1) {
        if (tid < s) { r1[tid] += r1[tid+s]; r2[tid] += r2[tid+s]; }
        __syncthreads();
    }
    float corr = r1[0] / (r2[0] + 1e-8f);
    hout[(size_t)(b*64 + n)*MM + tid] = hr - corr;
}

// ---------------------------------------------------------------------------
extern "C" void kernel_launch(void* const* d_in, const int* in_sizes, int n_in,
                              void* d_out, int out_size)
{
    const float* marg  = (const float*)d_in[0];
    const float* xg    = (const float*)d_in[1];
    const float* convw = (const float*)d_in[2];
    const float* convb = (const float*)d_in[3];
    const float* fcw   = (const float*)d_in[4];
    const float* fcb   = (const float*)d_in[5];
    const float* ln0g  = (const float*)d_in[6];
    const float* ln0b  = (const float*)d_in[7];
    const float* pos   = (const float*)d_in[8];
    const float* qkvw  = (const float*)d_in[9];
    const float* qkvb  = (const float*)d_in[10];
    const float* outw  = (const float*)d_in[11];
    const float* outb  = (const float*)d_in[12];
    const float* ln1g  = (const float*)d_in[13];
    const float* ln1b  = (const float*)d_in[14];
    const float* ff1w  = (const float*)d_in[15];
    const float* ff1b  = (const float*)d_in[16];
    const float* ff2w  = (const float*)d_in[17];
    const float* ff2b  = (const float*)d_in[18];
    const float* ln2g  = (const float*)d_in[19];
    const float* ln2b  = (const float*)d_in[20];
    const float* uw    = (const float*)d_in[21];
    const float* ub    = (const float*)d_in[22];
    const float* hw    = (const float*)d_in[23];
    const float* hb    = (const float*)d_in[24];

    float *xs, *qkv, *attn, *tmp, *ff, *hraw;
    cudaGetSymbolAddress((void**)&xs,   g_xs);
    cudaGetSymbolAddress((void**)&qkv,  g_qkv);
    cudaGetSymbolAddress((void**)&attn, g_attn);
    cudaGetSymbolAddress((void**)&tmp,  g_tmp);
    cudaGetSymbolAddress((void**)&ff,   g_ff);
    cudaGetSymbolAddress((void**)&hraw, g_hraw);

    float* out = (float*)d_out;

    embed_kernel<<<TOK, 256>>>(marg, convw, convb, fcw, fcb, ln0g, ln0b, pos, xs);

    dim3 gM((unsigned)((TOK + GT - 1) / GT));   // 17 M-tiles
    for (int l = 0; l < LL; l++) {
        gemm_bias<0><<<dim3(3*DD/GT, gM.x), 256>>>(xs, qkvw + (size_t)l*3*DD*DD,
                                                   qkvb + l*3*DD, qkv, TOK, 3*DD, DD);
        attn_kernel<<<BB*HH, 256>>>(qkv, attn);
        gemm_bias<0><<<dim3(DD/GT, gM.x), 256>>>(attn, outw + (size_t)l*DD*DD,
                                                 outb + l*DD, tmp, TOK, DD, DD);
        ln_res_kernel<<<TOK, 256>>>(tmp, ln1g + l*DD, ln1b + l*DD, xs);
        gemm_bias<1><<<dim3(DFF/GT, gM.x), 256>>>(xs, ff1w + (size_t)l*DFF*DD,
                                                  ff1b + l*DFF, ff, TOK, DFF, DD);
        gemm_bias<0><<<dim3(DD/GT, gM.x), 256>>>(ff, ff2w + (size_t)l*DD*DFF,
                                                 ff2b + l*DD, tmp, TOK, DD, DFF);
        ln_res_kernel<<<TOK, 256>>>(tmp, ln2g + l*DD, ln2b + l*DD, xs);
    }

    // u_pot: directly into output region [1040, 256]
    gemm_bias<0><<<dim3(MM/GT, gM.x), 256>>>(xs, uw, ub, out, TOK, MM, DD);
    // h_raw for all tokens (rows with pos<64 consumed by tail)
    gemm_bias<0><<<dim3(MM/GT, gM.x), 256>>>(xs, hw, hb, hraw, TOK, MM, DD);
    // h_pot into output region offset 1040*256
    tail_kernel<<<BB*64, 256>>>(hraw, marg, xg, out + (size_t)TOK*MM);
}

// round 3
// speedup vs baseline: 1.4896x; 1.4896x over previous
#include <cuda_runtime.h>
#include <cuda_bf16.h>
#include <math.h>
#include <stdint.h>

// Problem constants
#define BB    16
#define NP1   65
#define TOK   (BB*NP1)      // 1040
#define MM    256
#define DD    512
#define HH    8
#define DH    64
#define LL    3
#define DFF   2048

// ---------------- weight arena offsets (elements) ---------------------------
#define W_QKV 0
#define W_OUT 2359296
#define W_FF1 3145728
#define W_FF2 6291456
#define W_U   9437184
#define W_H   9568256
#define W_TOT 9699328

// ---------------- scratch (device globals; no allocation allowed) ----------
__device__ __align__(128) float          g_xs  [TOK*DD];
__device__ __align__(128) __nv_bfloat16  g_xsh [TOK*DD];
__device__ __align__(128) __nv_bfloat16  g_xsl [TOK*DD];
__device__ __align__(128) float          g_qkv [TOK*3*DD];
__device__ __align__(128) __nv_bfloat16  g_ath [TOK*DD];
__device__ __align__(128) __nv_bfloat16  g_atl [TOK*DD];
__device__ __align__(128) float          g_tmp [TOK*DD];
__device__ __align__(128) __nv_bfloat16  g_ffh [TOK*DFF];
__device__ __align__(128) __nv_bfloat16  g_ffl [TOK*DFF];
__device__ __align__(128) float          g_hraw[TOK*MM];
__device__ __align__(128) __nv_bfloat16  g_wh  [W_TOT];
__device__ __align__(128) __nv_bfloat16  g_wl  [W_TOT];

// ---------------- PTX helpers (all portable to bare sm_103) -----------------
__device__ __forceinline__ uint32_t s2u(const void* p) {
    uint32_t a;
    asm("{ .reg .u64 t; cvta.to.shared.u64 t, %1; cvt.u32.u64 %0, t; }" : "=r"(a) : "l"(p));
    return a;
}
__device__ __forceinline__ void cp16(uint32_t dst, const void* src) {
    unsigned long long g = (unsigned long long)__cvta_generic_to_global(src);
    asm volatile("cp.async.cg.shared.global [%0], [%1], 16;" :: "r"(dst), "l"(g) : "memory");
}
#define CP_COMMIT() asm volatile("cp.async.commit_group;" ::: "memory")
#define CP_WAIT(n)  asm volatile("cp.async.wait_group %0;" :: "n"(n) : "memory")

__device__ __forceinline__ void ldm4(uint32_t* r, uint32_t a) {
    asm volatile("ldmatrix.sync.aligned.m8n8.x4.shared.b16 {%0,%1,%2,%3}, [%4];"
        : "=r"(r[0]), "=r"(r[1]), "=r"(r[2]), "=r"(r[3]) : "r"(a));
}
__device__ __forceinline__ void mma16816(float* c, const uint32_t* a, uint32_t b0, uint32_t b1) {
    asm volatile("mma.sync.aligned.m16n8k16.row.col.f32.bf16.bf16.f32 "
        "{%0,%1,%2,%3}, {%4,%5,%6,%7}, {%8,%9}, {%0,%1,%2,%3};"
        : "+f"(c[0]), "+f"(c[1]), "+f"(c[2]), "+f"(c[3])
        : "r"(a[0]), "r"(a[1]), "r"(a[2]), "r"(a[3]), "r"(b0), "r"(b1));
}

// ---------------- weight split kernel --------------------------------------
__global__ __launch_bounds__(256)
void split_kernel(const float* __restrict__ src, __nv_bfloat16* __restrict__ dh,
                  __nv_bfloat16* __restrict__ dl, int n)
{
    int i = blockIdx.x*256 + threadIdx.x;
    if (i < n) {
        float x = src[i];
        __nv_bfloat16 h = __float2bfloat16_rn(x);
        dh[i] = h;
        dl[i] = __float2bfloat16_rn(x - __bfloat162float(h));
    }
}

// ---------------- HMMA GEMM: C[m,n] = sum_k A[m,k]*W[n,k] + bias ------------
// Block 128(M)x64(N), 8 warps in 4x2 grid, warp tile 32x32, K-chunk 32.
// 3-term bf16 split: Ah*Wh + Ah*Wl + Al*Wh.
// EPI 0: fp32 + b0 -> C0[m*N+n]
// EPI 1: gelu(v+b0) -> hi/lo bf16 (Ch, Cl)
// EPI 2: n<256 -> C0[m*256+n]+b0 ; n>=256 -> C1[m*256+n-256]+b1
#define LDS_B   80          // padded row stride bytes (32 bf16 = 64B payload + 16B pad)
#define A_HI    0
#define A_LO    10240       // 128*80
#define W_HI    20480
#define W_LO    25600       // + 64*80
#define STG_B   30720
#define NSTG    3
#define SMEM_SZ (NSTG*STG_B)

__device__ __forceinline__ void load_chunk(uint32_t sb, int stage,
    const __nv_bfloat16* Ah, const __nv_bfloat16* Al,
    const __nv_bfloat16* Wh, const __nv_bfloat16* Wl,
    int m0, int n0, int k0, int M, int K, int tid)
{
    uint32_t st = sb + stage*STG_B;
    // A: 128 rows x 4 16B-chunks, hi+lo : 2 each per thread
    #pragma unroll
    for (int p = 0; p < 2; p++) {
        int idx = tid + p*256;          // 0..511
        int row = idx >> 2, g = idx & 3;
        int ar = m0 + row; if (ar >= M) ar = M - 1;
        size_t off = (size_t)ar*K + k0 + g*8;
        uint32_t d = row*LDS_B + g*16;
        cp16(st + A_HI + d, Ah + off);
        cp16(st + A_LO + d, Al + off);
    }
    // W: 64 rows x 4 chunks, hi+lo : 1 each per thread
    {
        int row = tid >> 2, g = tid & 3;
        size_t off = (size_t)(n0 + row)*K + k0 + g*8;
        uint32_t d = row*LDS_B + g*16;
        cp16(st + W_HI + d, Wh + off);
        cp16(st + W_LO + d, Wl + off);
    }
}

template<int EPI>
__global__ __launch_bounds__(256)
void mma_gemm(const __nv_bfloat16* __restrict__ Ah, const __nv_bfloat16* __restrict__ Al,
              const __nv_bfloat16* __restrict__ Wh, const __nv_bfloat16* __restrict__ Wl,
              const float* __restrict__ b0, const float* __restrict__ b1,
              float* __restrict__ C0, float* __restrict__ C1,
              __nv_bfloat16* __restrict__ Ch, __nv_bfloat16* __restrict__ Cl,
              int M, int N, int K)
{
    extern __shared__ char smem[];
    uint32_t sb = s2u(smem);
    int tid = threadIdx.x, wid = tid >> 5, lane = tid & 31;
    int wm = wid >> 1, wn = wid & 1;
    int m0 = blockIdx.y * 128, n0 = blockIdx.x * 64;
    const int NC = K >> 5;          // 32-wide K chunks

    float c[2][4][4];
    #pragma unroll
    for (int i = 0; i < 2; i++)
        #pragma unroll
        for (int j = 0; j < 4; j++)
            #pragma unroll
            for (int q = 0; q < 4; q++) c[i][j][q] = 0.f;

    load_chunk(sb, 0, Ah, Al, Wh, Wl, m0, n0, 0,  M, K, tid); CP_COMMIT();
    load_chunk(sb, 1, Ah, Al, Wh, Wl, m0, n0, 32, M, K, tid); CP_COMMIT();

    // per-lane ldmatrix base offsets (within a stage)
    uint32_t lrow = (lane & 15);
    uint32_t koff = (lane >> 4) * 16;

    for (int cc = 0; cc < NC; cc++) {
        if (cc + 2 < NC)
            load_chunk(sb, (cc+2)%NSTG, Ah, Al, Wh, Wl, m0, n0, (cc+2)*32, M, K, tid);
        CP_COMMIT();
        CP_WAIT(2);
        __syncthreads();

        uint32_t st = sb + (cc % NSTG)*STG_B;
        #pragma unroll
        for (int ks = 0; ks < 2; ks++) {
            uint32_t kb = ks*32 + koff;
            uint32_t ah[2][4], al[2][4];
            #pragma unroll
            for (int i = 0; i < 2; i++) {
                uint32_t ra = st + (wm*32 + i*16 + lrow)*LDS_B + kb;
                ldm4(ah[i], ra + A_HI);
                ldm4(al[i], ra + A_LO);
            }
            #pragma unroll
            for (int j2 = 0; j2 < 2; j2++) {
                uint32_t rb = st + (wn*32 + j2*16 + lrow)*LDS_B + kb;
                uint32_t bh[4], bl[4];
                ldm4(bh, rb + W_HI);
                ldm4(bl, rb + W_LO);
                #pragma unroll
                for (int i = 0; i < 2; i++) {
                    #pragma unroll
                    for (int jj = 0; jj < 2; jj++) {
                        float* acc = c[i][2*j2 + jj];
                        mma16816(acc, ah[i], bh[jj], bh[jj+2]);
                        mma16816(acc, ah[i], bl[jj], bl[jj+2]);
                        mma16816(acc, al[i], bh[jj], bh[jj+2]);
                    }
                }
            }
        }
        __syncthreads();
    }

    // epilogue
    int rbase = m0 + wm*32 + (lane >> 2);
    int cbase = n0 + wn*32 + 2*(lane & 3);
    #pragma unroll
    for (int i = 0; i < 2; i++) {
        #pragma unroll
        for (int j = 0; j < 4; j++) {
            int col = cbase + j*8;
            float bb0 = b0[col], bb1 = b0[col+1];
            #pragma unroll
            for (int half = 0; half < 2; half++) {
                int r = rbase + i*16 + half*8;
                if (r >= M) continue;
                float v0 = c[i][j][2*half + 0] + bb0;
                float v1 = c[i][j][2*half + 1] + bb1;
                if (EPI == 0) {
                    *(float2*)(C0 + (size_t)r*N + col) = make_float2(v0, v1);
                } else if (EPI == 1) {
                    v0 = 0.5f*v0*(1.0f + erff(v0*0.70710678118654752f));
                    v1 = 0.5f*v1*(1.0f + erff(v1*0.70710678118654752f));
                    __nv_bfloat16 h0 = __float2bfloat16_rn(v0);
                    __nv_bfloat16 h1 = __float2bfloat16_rn(v1);
                    __nv_bfloat162 hp; hp.x = h0; hp.y = h1;
                    __nv_bfloat162 lp;
                    lp.x = __float2bfloat16_rn(v0 - __bfloat162float(h0));
                    lp.y = __float2bfloat16_rn(v1 - __bfloat162float(h1));
                    *(__nv_bfloat162*)(Ch + (size_t)r*N + col) = hp;
                    *(__nv_bfloat162*)(Cl + (size_t)r*N + col) = lp;
                } else {
                    if (col < 256) {
                        *(float2*)(C0 + (size_t)r*256 + col) = make_float2(v0, v1);
                    } else {
                        float u0 = c[i][j][2*half+0] + b1[col-256];
                        float u1 = c[i][j][2*half+1] + b1[col-255];
                        *(float2*)(C1 + (size_t)r*256 + (col-256)) = make_float2(u0, u1);
                    }
                }
            }
        }
    }
}

// ---------------- embed: conv-collapse + fc + LN + GELU + pos --------------
__global__ __launch_bounds__(256)
void embed_kernel(const float* __restrict__ marg, const float* __restrict__ conv_w,
                  const float* __restrict__ conv_b, const float* __restrict__ fc_w,
                  const float* __restrict__ fc_b, const float* __restrict__ ln_g,
                  const float* __restrict__ ln_b, const float* __restrict__ pos,
                  float* __restrict__ xs, __nv_bfloat16* __restrict__ xsh,
                  __nv_bfloat16* __restrict__ xsl)
{
    int row = blockIdx.x;
    int tid = threadIdx.x;
    __shared__ float red[256];
    __shared__ float e[128];

    const float* x = marg + (size_t)row * MM;
    red[tid] = x[tid];
    __syncthreads();
    for (int s = 128; s > 0; s >>= 1) { if (tid < s) red[tid] += red[tid+s]; __syncthreads(); }
    float S = red[0];
    __syncthreads();

    if (tid < 128) {
        float x0 = x[0], x1 = x[1], xm2 = x[MM-2], xm1 = x[MM-1];
        const float* w = conv_w + tid*5;
        float acc = w[0]*(S - xm2 - xm1) + w[1]*(S - xm1) + w[2]*S
                  + w[3]*(S - x0)        + w[4]*(S - x0 - x1);
        e[tid] = conv_b[tid] + acc * (1.0f/(float)MM);
    }
    __syncthreads();

    float t0 = fc_b[tid], t1 = fc_b[tid+256];
    #pragma unroll 4
    for (int c = 0; c < 128; c++) {
        float ec = e[c];
        t0 += ec * fc_w[c*DD + tid];
        t1 += ec * fc_w[c*DD + tid + 256];
    }

    red[tid] = t0 + t1; __syncthreads();
    for (int s = 128; s > 0; s >>= 1) { if (tid < s) red[tid] += red[tid+s]; __syncthreads(); }
    float mean = red[0] * (1.0f/(float)DD);
    __syncthreads();
    float d0 = t0 - mean, d1 = t1 - mean;
    red[tid] = d0*d0 + d1*d1; __syncthreads();
    for (int s = 128; s > 0; s >>= 1) { if (tid < s) red[tid] += red[tid+s]; __syncthreads(); }
    float inv = rsqrtf(red[0] * (1.0f/(float)DD) + 1e-5f);

    float y0 = d0*inv*ln_g[tid]     + ln_b[tid];
    float y1 = d1*inv*ln_g[tid+256] + ln_b[tid+256];
    y0 = 0.5f*y0*(1.0f + erff(y0*0.70710678118654752f));
    y1 = 0.5f*y1*(1.0f + erff(y1*0.70710678118654752f));

    int p = row % NP1;
    float v0 = y0 + pos[p*DD + tid];
    float v1 = y1 + pos[p*DD + tid + 256];
    size_t base = (size_t)row*DD;
    xs[base + tid] = v0; xs[base + tid + 256] = v1;
    __nv_bfloat16 h0 = __float2bfloat16_rn(v0), h1 = __float2bfloat16_rn(v1);
    xsh[base + tid] = h0;        xsh[base + tid + 256] = h1;
    xsl[base + tid] = __float2bfloat16_rn(v0 - __bfloat162float(h0));
    xsl[base + tid + 256] = __float2bfloat16_rn(v1 - __bfloat162float(h1));
}

// ---------------- attention: one block per (b,h) ---------------------------
__global__ __launch_bounds__(256)
void attn_kernel(const float* __restrict__ qkv, __nv_bfloat16* __restrict__ ah,
                 __nv_bfloat16* __restrict__ al)
{
    int bh = blockIdx.x;
    int b = bh >> 3, h = bh & 7;
    __shared__ float Ks[NP1][65];
    __shared__ float Vs[NP1][64];
    __shared__ float Ps[8][72];

    int tid = threadIdx.x, lane = tid & 31, w = tid >> 5;

    for (int idx = tid; idx < NP1*64; idx += 256) {
        int j = idx >> 6, k = idx & 63;
        size_t base = ((size_t)(b*NP1 + j))*(3*DD) + h*DH + k;
        Ks[j][k] = qkv[base + DD];
        Vs[j][k] = qkv[base + 2*DD];
    }
    __syncthreads();

    const float scale = 0.125f;
    for (int qi = w; qi < NP1; qi += 8) {
        size_t qbase = ((size_t)(b*NP1 + qi))*(3*DD) + h*DH;
        float2 qp = *(const float2*)(qkv + qbase + 2*lane);
        float qa = qp.x, qb = qp.y;

        float s0 = 0.f, s1 = 0.f, s2 = 0.f;
        #pragma unroll
        for (int k = 0; k < 64; k++) {
            float qv = __shfl_sync(0xffffffffu, (k & 1) ? qb : qa, k >> 1);
            s0 = fmaf(qv, Ks[lane][k],      s0);
            s1 = fmaf(qv, Ks[lane + 32][k], s1);
            s2 = fmaf(qv, Ks[64][k],        s2);
        }
        s0 *= scale; s1 *= scale; s2 *= scale;

        float mx = fmaxf(fmaxf(s0, s1), s2);
        #pragma unroll
        for (int o = 16; o > 0; o >>= 1) mx = fmaxf(mx, __shfl_xor_sync(0xffffffffu, mx, o));
        float e0 = expf(s0 - mx), e1 = expf(s1 - mx), e2 = expf(s2 - mx);
        float ls = e0 + e1;
        #pragma unroll
        for (int o = 16; o > 0; o >>= 1) ls += __shfl_xor_sync(0xffffffffu, ls, o);
        float rinv = 1.0f / (ls + e2);

        Ps[w][lane]      = e0 * rinv;
        Ps[w][lane + 32] = e1 * rinv;
        if (lane == 0) Ps[w][64] = e2 * rinv;
        __syncwarp();

        float o0 = 0.f, o1 = 0.f;
        #pragma unroll 5
        for (int j = 0; j < NP1; j++) {
            float pj = Ps[w][j];
            o0 = fmaf(pj, Vs[j][lane],      o0);
            o1 = fmaf(pj, Vs[j][lane + 32], o1);
        }
        size_t obase = ((size_t)(b*NP1 + qi))*DD + h*DH;
        __nv_bfloat16 h0 = __float2bfloat16_rn(o0), h1 = __float2bfloat16_rn(o1);
        ah[obase + lane]      = h0;
        ah[obase + lane + 32] = h1;
        al[obase + lane]      = __float2bfloat16_rn(o0 - __bfloat162float(h0));
        al[obase + lane + 32] = __float2bfloat16_rn(o1 - __bfloat162float(h1));
        __syncwarp();
    }
}

// ---------------- residual + LayerNorm (in place on xs), emits hi/lo -------
__global__ __launch_bounds__(256)
void ln_res_kernel(const float* __restrict__ add, const float* __restrict__ g,
                   const float* __restrict__ bta, float* __restrict__ xs,
                   __nv_bfloat16* __restrict__ xsh, __nv_bfloat16* __restrict__ xsl)
{
    int row = blockIdx.x, tid = threadIdx.x;
    __shared__ float red[256];
    size_t base = (size_t)row*DD;
    float v0 = xs[base + tid]       + add[base + tid];
    float v1 = xs[base + tid + 256] + add[base + tid + 256];

    red[tid] = v0 + v1; __syncthreads();
    for (int s = 128; s > 0; s >>= 1) { if (tid < s) red[tid] += red[tid+s]; __syncthreads(); }
    float mean = red[0] * (1.0f/(float)DD);
    __syncthreads();
    float d0 = v0 - mean, d1 = v1 - mean;
    red[tid] = d0*d0 + d1*d1; __syncthreads();
    for (int s = 128; s > 0; s >>= 1) { if (tid < s) red[tid] += red[tid+s]; __syncthreads(); }
    float inv = rsqrtf(red[0] * (1.0f/(float)DD) + 1e-5f);

    float y0 = d0*inv*g[tid]       + bta[tid];
    float y1 = d1*inv*g[tid + 256] + bta[tid + 256];
    xs[base + tid] = y0; xs[base + tid + 256] = y1;
    __nv_bfloat16 h0 = __float2bfloat16_rn(y0), h1 = __float2bfloat16_rn(y1);
    xsh[base + tid] = h0;        xsh[base + tid + 256] = h1;
    xsl[base + tid] = __float2bfloat16_rn(y0 - __bfloat162float(h0));
    xsl[base + tid + 256] = __float2bfloat16_rn(y1 - __bfloat162float(h1));
}

// ---------------- MMOT tail: closed-form truncated-geometric softmax -------
__global__ __launch_bounds__(256)
void tail_kernel(const float* __restrict__ hraw, const float* __restrict__ marg,
                 const float* __restrict__ xg, float* __restrict__ hout)
{
    int blk = blockIdx.x;
    int b = blk >> 6, n = blk & 63;
    int tid = threadIdx.x;
    int tok = b*NP1 + n;

    float hr = hraw[(size_t)tok*MM + tid];
    const float DELTA = 6.0f/255.0f;
    float t = hr * (DELTA / 0.01f);
    float q = expf(-fabsf(t));

    float S0 = 1.f, S1 = 0.f, p = q, mcnt = 1.f;
    #pragma unroll
    for (int it = 0; it < 8; it++) {
        S1 = S1 + p*(S1 + mcnt*S0);
        S0 = S0 + p*S0;
        p  = p*p;
        mcnt *= 2.f;
    }
    float f = S1 / S0;
    if (t < 0.f) f = 255.f - f;

    float expected = -3.f + DELTA * f;
    float drift = expected - xg[tid];
    float mu = marg[(size_t)tok*MM + tid];

    __shared__ float r1[256], r2[256];
    r1[tid] = mu * drift; r2[tid] = mu;
    __syncthreads();
    for (int s = 128; s > 0; s >>= 1) {
        if (tid < s) { r1[tid] += r1[tid+s]; r2[tid] += r2[tid+s]; }
        __syncthreads();
    }
    float corr = r1[0] / (r2[0] + 1e-8f);
    hout[(size_t)(b*64 + n)*MM + tid] = hr - corr;
}

// ---------------------------------------------------------------------------
extern "C" void kernel_launch(void* const* d_in, const int* in_sizes, int n_in,
                              void* d_out, int out_size)
{
    const float* marg  = (const float*)d_in[0];
    const float* xg    = (const float*)d_in[1];
    const float* convw = (const float*)d_in[2];
    const float* convb = (const float*)d_in[3];
    const float* fcw   = (const float*)d_in[4];
    const float* fcb   = (const float*)d_in[5];
    const float* ln0g  = (const float*)d_in[6];
    const float* ln0b  = (const float*)d_in[7];
    const float* pos   = (const float*)d_in[8];
    const float* qkvw  = (const float*)d_in[9];
    const float* qkvb  = (const float*)d_in[10];
    const float* outw  = (const float*)d_in[11];
    const float* outb  = (const float*)d_in[12];
    const float* ln1g  = (const float*)d_in[13];
    const float* ln1b  = (const float*)d_in[14];
    const float* ff1w  = (const float*)d_in[15];
    const float* ff1b  = (const float*)d_in[16];
    const float* ff2w  = (const float*)d_in[17];
    const float* ff2b  = (const float*)d_in[18];
    const float* ln2g  = (const float*)d_in[19];
    const float* ln2b  = (const float*)d_in[20];
    const float* uw    = (const float*)d_in[21];
    const float* ub    = (const float*)d_in[22];
    const float* hw    = (const float*)d_in[23];
    const float* hb    = (const float*)d_in[24];

    float *xs, *qkv, *tmp, *hraw;
    __nv_bfloat16 *xsh, *xsl, *ath, *atl, *ffh, *ffl, *wh, *wl;
    cudaGetSymbolAddress((void**)&xs,   g_xs);
    cudaGetSymbolAddress((void**)&xsh,  g_xsh);
    cudaGetSymbolAddress((void**)&xsl,  g_xsl);
    cudaGetSymbolAddress((void**)&qkv,  g_qkv);
    cudaGetSymbolAddress((void**)&ath,  g_ath);
    cudaGetSymbolAddress((void**)&atl,  g_atl);
    cudaGetSymbolAddress((void**)&tmp,  g_tmp);
    cudaGetSymbolAddress((void**)&ffh,  g_ffh);
    cudaGetSymbolAddress((void**)&ffl,  g_ffl);
    cudaGetSymbolAddress((void**)&hraw, g_hraw);
    cudaGetSymbolAddress((void**)&wh,   g_wh);
    cudaGetSymbolAddress((void**)&wl,   g_wl);

    float* out = (float*)d_out;

    cudaFuncSetAttribute(mma_gemm<0>, cudaFuncAttributeMaxDynamicSharedMemorySize, SMEM_SZ);
    cudaFuncSetAttribute(mma_gemm<1>, cudaFuncAttributeMaxDynamicSharedMemorySize, SMEM_SZ);
    cudaFuncSetAttribute(mma_gemm<2>, cudaFuncAttributeMaxDynamicSharedMemorySize, SMEM_SZ);

    // split weights fp32 -> bf16 hi/lo arena
    struct { const float* s; int off; int n; } cv[6] = {
        { qkvw, W_QKV, LL*3*DD*DD }, { outw, W_OUT, LL*DD*DD },
        { ff1w, W_FF1, LL*DFF*DD },  { ff2w, W_FF2, LL*DD*DFF },
        { uw,   W_U,   MM*DD },      { hw,   W_H,   MM*DD } };
    for (int i = 0; i < 6; i++)
        split_kernel<<<(cv[i].n + 255)/256, 256>>>(cv[i].s, wh + cv[i].off, wl + cv[i].off, cv[i].n);

    embed_kernel<<<TOK, 256>>>(marg, convw, convb, fcw, fcb, ln0g, ln0b, pos, xs, xsh, xsl);

    const unsigned GY = (TOK + 127) / 128;   // 9
    for (int l = 0; l < LL; l++) {
        mma_gemm<0><<<dim3(3*DD/64, GY), 256, SMEM_SZ>>>(
            xsh, xsl, wh + W_QKV + (size_t)l*3*DD*DD, wl + W_QKV + (size_t)l*3*DD*DD,
            qkvb + l*3*DD, nullptr, qkv, nullptr, nullptr, nullptr, TOK, 3*DD, DD);
        attn_kernel<<<BB*HH, 256>>>(qkv, ath, atl);
        mma_gemm<0><<<dim3(DD/64, GY), 256, SMEM_SZ>>>(
            ath, atl, wh + W_OUT + (size_t)l*DD*DD, wl + W_OUT + (size_t)l*DD*DD,
            outb + l*DD, nullptr, tmp, nullptr, nullptr, nullptr, TOK, DD, DD);
        ln_res_kernel<<<TOK, 256>>>(tmp, ln1g + l*DD, ln1b + l*DD, xs, xsh, xsl);
        mma_gemm<1><<<dim3(DFF/64, GY), 256, SMEM_SZ>>>(
            xsh, xsl, wh + W_FF1 + (size_t)l*DFF*DD, wl + W_FF1 + (size_t)l*DFF*DD,
            ff1b + l*DFF, nullptr, nullptr, nullptr, ffh, ffl, TOK, DFF, DD);
        mma_gemm<0><<<dim3(DD/64, GY), 256, SMEM_SZ>>>(
            ffh, ffl, wh + W_FF2 + (size_t)l*DD*DFF, wl + W_FF2 + (size_t)l*DD*DFF,
            ff2b + l*DD, nullptr, tmp, nullptr, nullptr, nullptr, TOK, DD, DFF);
        ln_res_kernel<<<TOK, 256>>>(tmp, ln2g + l*DD, ln2b + l*DD, xs, xsh, xsl);
    }

    // merged u/h GEMM: W rows 0..255 = u_w, 256..511 = h_w (contiguous in arena)
    mma_gemm<2><<<dim3(512/64, GY), 256, SMEM_SZ>>>(
        xsh, xsl, wh + W_U, wl + W_U, ub, hb, out, hraw, nullptr, nullptr, TOK, 512, DD);

    tail_kernel<<<BB*64, 256>>>(hraw, marg, xg, out + (size_t)TOK*MM);
}

// round 4
// speedup vs baseline: 2.2081x; 1.4823x over previous
#include <cuda_runtime.h>
#include <cuda_bf16.h>
#include <math.h>
#include <stdint.h>

// Problem constants
#define BB    16
#define NP1   65
#define TOK   (BB*NP1)      // 1040
#define MM    256
#define DD    512
#define HH    8
#define DH    64
#define LL    3
#define DFF   2048

// ---------------- weight arena offsets (elements) ---------------------------
#define W_QKV 0
#define W_OUT 2359296
#define W_FF1 3145728
#define W_FF2 6291456
#define W_U   9437184
#define W_H   9568256
#define W_TOT 9699328

// ---------------- scratch (device globals; no allocation allowed) ----------
__device__ __align__(128) float          g_xs  [TOK*DD];
__device__ __align__(128) __nv_bfloat16  g_xsh [TOK*DD];
__device__ __align__(128) __nv_bfloat16  g_xsl [TOK*DD];
__device__ __align__(128) float          g_qkv [TOK*3*DD];
__device__ __align__(128) __nv_bfloat16  g_ath [TOK*DD];
__device__ __align__(128) __nv_bfloat16  g_atl [TOK*DD];
__device__ __align__(128) float          g_tmp [TOK*DD];
__device__ __align__(128) __nv_bfloat16  g_ffh [TOK*DFF];
__device__ __align__(128) __nv_bfloat16  g_ffl [TOK*DFF];
__device__ __align__(128) float          g_hraw[TOK*MM];
__device__ __align__(128) __nv_bfloat16  g_wh  [W_TOT];
__device__ __align__(128) __nv_bfloat16  g_wl  [W_TOT];

// ---------------- PTX helpers (portable to bare sm_103) ---------------------
__device__ __forceinline__ uint32_t s2u(const void* p) {
    uint32_t a;
    asm("{ .reg .u64 t; cvta.to.shared.u64 t, %1; cvt.u32.u64 %0, t; }" : "=r"(a) : "l"(p));
    return a;
}
__device__ __forceinline__ void cp16(uint32_t dst, const void* src) {
    unsigned long long g = (unsigned long long)__cvta_generic_to_global(src);
    asm volatile("cp.async.cg.shared.global [%0], [%1], 16;" :: "r"(dst), "l"(g) : "memory");
}
#define CP_COMMIT() asm volatile("cp.async.commit_group;" ::: "memory")
#define CP_WAIT(n)  asm volatile("cp.async.wait_group %0;" :: "n"(n) : "memory")

__device__ __forceinline__ void ldm4(uint32_t* r, uint32_t a) {
    asm volatile("ldmatrix.sync.aligned.m8n8.x4.shared.b16 {%0,%1,%2,%3}, [%4];"
        : "=r"(r[0]), "=r"(r[1]), "=r"(r[2]), "=r"(r[3]) : "r"(a));
}
__device__ __forceinline__ void mma16816(float* c, const uint32_t* a, uint32_t b0, uint32_t b1) {
    asm volatile("mma.sync.aligned.m16n8k16.row.col.f32.bf16.bf16.f32 "
        "{%0,%1,%2,%3}, {%4,%5,%6,%7}, {%8,%9}, {%0,%1,%2,%3};"
        : "+f"(c[0]), "+f"(c[1]), "+f"(c[2]), "+f"(c[3])
        : "r"(a[0]), "r"(a[1]), "r"(a[2]), "r"(a[3]), "r"(b0), "r"(b1));
}

// ---------------- fused weight split: fp32 arena -> bf16 hi/lo --------------
__global__ __launch_bounds__(256)
void split_all(const float* __restrict__ qkvw, const float* __restrict__ outw,
               const float* __restrict__ ff1w, const float* __restrict__ ff2w,
               const float* __restrict__ uw,   const float* __restrict__ hw,
               __nv_bfloat16* __restrict__ wh, __nv_bfloat16* __restrict__ wl)
{
    size_t i = ((size_t)blockIdx.x*256 + threadIdx.x)*4;
    if (i >= W_TOT) return;
    const float* src;
    if      (i < W_OUT) src = qkvw + i;
    else if (i < W_FF1) src = outw + (i - W_OUT);
    else if (i < W_FF2) src = ff1w + (i - W_FF1);
    else if (i < W_U)   src = ff2w + (i - W_FF2);
    else if (i < W_H)   src = uw   + (i - W_U);
    else                src = hw   + (i - W_H);
    float4 v = *(const float4*)src;
    __nv_bfloat16 h0 = __float2bfloat16_rn(v.x), h1 = __float2bfloat16_rn(v.y);
    __nv_bfloat16 h2 = __float2bfloat16_rn(v.z), h3 = __float2bfloat16_rn(v.w);
    __nv_bfloat162 hp0; hp0.x = h0; hp0.y = h1;
    __nv_bfloat162 hp1; hp1.x = h2; hp1.y = h3;
    ((__nv_bfloat162*)(wh + i))[0] = hp0;
    ((__nv_bfloat162*)(wh + i))[1] = hp1;
    __nv_bfloat162 lp0, lp1;
    lp0.x = __float2bfloat16_rn(v.x - __bfloat162float(h0));
    lp0.y = __float2bfloat16_rn(v.y - __bfloat162float(h1));
    lp1.x = __float2bfloat16_rn(v.z - __bfloat162float(h2));
    lp1.y = __float2bfloat16_rn(v.w - __bfloat162float(h3));
    ((__nv_bfloat162*)(wl + i))[0] = lp0;
    ((__nv_bfloat162*)(wl + i))[1] = lp1;
}

// ---------------- HMMA GEMM: C[m,n] = sum_k A[m,k]*W[n,k] + bias ------------
// Templated tile: BM x BN (BM == BN), 2(M) x BN/32(N) warps, warp tile (BM/2)x32.
// 2-stage cp.async pipeline, K-chunk 32. 3-term bf16 split: Ah*Wh + Ah*Wl + Al*Wh.
// EPI 0: fp32 + b0 -> C0[m*N+n]
// EPI 1: gelu(v+b0) -> hi/lo bf16 (Ch, Cl)
// EPI 2: n<256 -> C0[m*256+n]+b0 ; n>=256 -> C1[m*256+n-256]+b1
#define LDS_B 80     // padded row stride (64B payload + 16B pad)

template<int BM, int BN>
__device__ __forceinline__ void load_chunk(uint32_t sb, int stage,
    const __nv_bfloat16* Ah, const __nv_bfloat16* Al,
    const __nv_bfloat16* Wh, const __nv_bfloat16* Wl,
    int m0, int n0, int k0, int M, int K, int tid)
{
    constexpr int AS_LO = BM*LDS_B;
    constexpr int WS_HI = 2*BM*LDS_B;
    constexpr int WS_LO = (2*BM+BN)*LDS_B;
    constexpr int STG   = (2*BM+2*BN)*LDS_B;
    constexpr int NTHR  = 2*BN;
    uint32_t st = sb + stage*STG;
    #pragma unroll
    for (int p = 0; p < 2; p++) {
        int idx = tid + p*NTHR;             // covers BM*4 granules (BM==BN)
        int row = idx >> 2, g = idx & 3;
        int ar = m0 + row; if (ar >= M) ar = M - 1;
        size_t off = (size_t)ar*K + k0 + g*8;
        uint32_t d = row*LDS_B + g*16;
        cp16(st + d,         Ah + off);
        cp16(st + AS_LO + d, Al + off);
    }
    #pragma unroll
    for (int p = 0; p < 2; p++) {
        int idx = tid + p*NTHR;
        int row = idx >> 2, g = idx & 3;
        size_t off = (size_t)(n0 + row)*K + k0 + g*8;
        uint32_t d = row*LDS_B + g*16;
        cp16(st + WS_HI + d, Wh + off);
        cp16(st + WS_LO + d, Wl + off);
    }
}

template<int EPI, int BM, int BN>
__global__ __launch_bounds__(2*BN, 2)
void mma_gemm(const __nv_bfloat16* __restrict__ Ah, const __nv_bfloat16* __restrict__ Al,
              const __nv_bfloat16* __restrict__ Wh, const __nv_bfloat16* __restrict__ Wl,
              const float* __restrict__ b0, const float* __restrict__ b1,
              float* __restrict__ C0, float* __restrict__ C1,
              __nv_bfloat16* __restrict__ Ch, __nv_bfloat16* __restrict__ Cl,
              int M, int N, int K)
{
    extern __shared__ char smem[];
    constexpr int IT = BM/32;           // m16 tiles per warp
    constexpr int WN = BN/32;           // warps in N
    constexpr int AS_LO = BM*LDS_B;
    constexpr int WS_HI = 2*BM*LDS_B;
    constexpr int STG   = (2*BM+2*BN)*LDS_B;
    uint32_t sb = s2u(smem);
    int tid = threadIdx.x, wid = tid >> 5, lane = tid & 31;
    int wm = wid / WN, wn = wid % WN;
    int m0 = blockIdx.y * BM, n0 = blockIdx.x * BN;
    const int NC = K >> 5;

    float c[IT][4][4];
    #pragma unroll
    for (int i = 0; i < IT; i++)
        #pragma unroll
        for (int j = 0; j < 4; j++)
            #pragma unroll
            for (int q = 0; q < 4; q++) c[i][j][q] = 0.f;

    load_chunk<BM,BN>(sb, 0, Ah, Al, Wh, Wl, m0, n0, 0,  M, K, tid); CP_COMMIT();
    load_chunk<BM,BN>(sb, 1, Ah, Al, Wh, Wl, m0, n0, 32, M, K, tid); CP_COMMIT();

    uint32_t lrow = (lane & 15);
    uint32_t koff = (lane >> 4) * 16;

    for (int cc = 0; cc < NC; cc++) {
        CP_WAIT(1);
        __syncthreads();
        uint32_t st = sb + (cc & 1)*STG;
        #pragma unroll
        for (int ks = 0; ks < 2; ks++) {
            uint32_t kb = ks*32 + koff;
            uint32_t bh[2][4], bl[2][4];
            #pragma unroll
            for (int j2 = 0; j2 < 2; j2++) {
                uint32_t rb = st + WS_HI + (wn*32 + j2*16 + lrow)*LDS_B + kb;
                ldm4(bh[j2], rb);
                ldm4(bl[j2], rb + BN*LDS_B);
            }
            #pragma unroll
            for (int i = 0; i < IT; i++) {
                uint32_t ra = st + (wm*(BM/2) + i*16 + lrow)*LDS_B + kb;
                uint32_t ah[4], al[4];
                ldm4(ah, ra);
                ldm4(al, ra + AS_LO);
                #pragma unroll
                for (int j2 = 0; j2 < 2; j2++) {
                    #pragma unroll
                    for (int jj = 0; jj < 2; jj++) {
                        float* acc = c[i][2*j2 + jj];
                        mma16816(acc, ah, bh[j2][jj], bh[j2][jj+2]);
                        mma16816(acc, ah, bl[j2][jj], bl[j2][jj+2]);
                        mma16816(acc, al, bh[j2][jj], bh[j2][jj+2]);
                    }
                }
            }
        }
        __syncthreads();
        if (cc + 2 < NC)
            load_chunk<BM,BN>(sb, cc & 1, Ah, Al, Wh, Wl, m0, n0, (cc+2)*32, M, K, tid);
        CP_COMMIT();
    }

    // epilogue
    int rbase = m0 + wm*(BM/2) + (lane >> 2);
    int cbase = n0 + wn*32 + 2*(lane & 3);
    #pragma unroll
    for (int i = 0; i < IT; i++) {
        #pragma unroll
        for (int j = 0; j < 4; j++) {
            int col = cbase + j*8;
            float bb0 = b0[col], bb1 = b0[col+1];
            #pragma unroll
            for (int half = 0; half < 2; half++) {
                int r = rbase + i*16 + half*8;
                if (r >= M) continue;
                float v0 = c[i][j][2*half + 0] + bb0;
                float v1 = c[i][j][2*half + 1] + bb1;
                if (EPI == 0) {
                    *(float2*)(C0 + (size_t)r*N + col) = make_float2(v0, v1);
                } else if (EPI == 1) {
                    v0 = 0.5f*v0*(1.0f + erff(v0*0.70710678118654752f));
                    v1 = 0.5f*v1*(1.0f + erff(v1*0.70710678118654752f));
                    __nv_bfloat16 h0 = __float2bfloat16_rn(v0);
                    __nv_bfloat16 h1 = __float2bfloat16_rn(v1);
                    __nv_bfloat162 hp; hp.x = h0; hp.y = h1;
                    __nv_bfloat162 lp;
                    lp.x = __float2bfloat16_rn(v0 - __bfloat162float(h0));
                    lp.y = __float2bfloat16_rn(v1 - __bfloat162float(h1));
                    *(__nv_bfloat162*)(Ch + (size_t)r*N + col) = hp;
                    *(__nv_bfloat162*)(Cl + (size_t)r*N + col) = lp;
                } else {
                    if (col < 256) {
                        *(float2*)(C0 + (size_t)r*256 + col) = make_float2(v0, v1);
                    } else {
                        float u0 = c[i][j][2*half+0] + b1[col-256];
                        float u1 = c[i][j][2*half+1] + b1[col-255];
                        *(float2*)(C1 + (size_t)r*256 + (col-256)) = make_float2(u0, u1);
                    }
                }
            }
        }
    }
}

// ---------------- embed: conv-collapse + fc + LN + GELU + pos --------------
__global__ __launch_bounds__(256)
void embed_kernel(const float* __restrict__ marg, const float* __restrict__ conv_w,
                  const float* __restrict__ conv_b, const float* __restrict__ fc_w,
                  const float* __restrict__ fc_b, const float* __restrict__ ln_g,
                  const float* __restrict__ ln_b, const float* __restrict__ pos,
                  float* __restrict__ xs, __nv_bfloat16* __restrict__ xsh,
                  __nv_bfloat16* __restrict__ xsl)
{
    int row = blockIdx.x;
    int tid = threadIdx.x;
    __shared__ float red[256];
    __shared__ float e[128];

    const float* x = marg + (size_t)row * MM;
    red[tid] = x[tid];
    __syncthreads();
    for (int s = 128; s > 0; s >>= 1) { if (tid < s) red[tid] += red[tid+s]; __syncthreads(); }
    float S = red[0];
    __syncthreads();

    if (tid < 128) {
        float x0 = x[0], x1 = x[1], xm2 = x[MM-2], xm1 = x[MM-1];
        const float* w = conv_w + tid*5;
        float acc = w[0]*(S - xm2 - xm1) + w[1]*(S - xm1) + w[2]*S
                  + w[3]*(S - x0)        + w[4]*(S - x0 - x1);
        e[tid] = conv_b[tid] + acc * (1.0f/(float)MM);
    }
    __syncthreads();

    float t0 = fc_b[tid], t1 = fc_b[tid+256];
    #pragma unroll 4
    for (int c = 0; c < 128; c++) {
        float ec = e[c];
        t0 += ec * fc_w[c*DD + tid];
        t1 += ec * fc_w[c*DD + tid + 256];
    }

    red[tid] = t0 + t1; __syncthreads();
    for (int s = 128; s > 0; s >>= 1) { if (tid < s) red[tid] += red[tid+s]; __syncthreads(); }
    float mean = red[0] * (1.0f/(float)DD);
    __syncthreads();
    float d0 = t0 - mean, d1 = t1 - mean;
    red[tid] = d0*d0 + d1*d1; __syncthreads();
    for (int s = 128; s > 0; s >>= 1) { if (tid < s) red[tid] += red[tid+s]; __syncthreads(); }
    float inv = rsqrtf(red[0] * (1.0f/(float)DD) + 1e-5f);

    float y0 = d0*inv*ln_g[tid]     + ln_b[tid];
    float y1 = d1*inv*ln_g[tid+256] + ln_b[tid+256];
    y0 = 0.5f*y0*(1.0f + erff(y0*0.70710678118654752f));
    y1 = 0.5f*y1*(1.0f + erff(y1*0.70710678118654752f));

    int p = row % NP1;
    float v0 = y0 + pos[p*DD + tid];
    float v1 = y1 + pos[p*DD + tid + 256];
    size_t base = (size_t)row*DD;
    xs[base + tid] = v0; xs[base + tid + 256] = v1;
    __nv_bfloat16 h0 = __float2bfloat16_rn(v0), h1 = __float2bfloat16_rn(v1);
    xsh[base + tid] = h0;        xsh[base + tid + 256] = h1;
    xsl[base + tid] = __float2bfloat16_rn(v0 - __bfloat162float(h0));
    xsl[base + tid + 256] = __float2bfloat16_rn(v1 - __bfloat162float(h1));
}

// ---------------- attention: one block per (b,h) ---------------------------
__global__ __launch_bounds__(256)
void attn_kernel(const float* __restrict__ qkv, __nv_bfloat16* __restrict__ ah,
                 __nv_bfloat16* __restrict__ al)
{
    int bh = blockIdx.x;
    int b = bh >> 3, h = bh & 7;
    __shared__ float Ks[NP1][65];
    __shared__ float Vs[NP1][64];
    __shared__ float Ps[8][72];

    int tid = threadIdx.x, lane = tid & 31, w = tid >> 5;

    for (int idx = tid; idx < NP1*64; idx += 256) {
        int j = idx >> 6, k = idx & 63;
        size_t base = ((size_t)(b*NP1 + j))*(3*DD) + h*DH + k;
        Ks[j][k] = qkv[base + DD];
        Vs[j][k] = qkv[base + 2*DD];
    }
    __syncthreads();

    const float scale = 0.125f;
    for (int qi = w; qi < NP1; qi += 8) {
        size_t qbase = ((size_t)(b*NP1 + qi))*(3*DD) + h*DH;
        float2 qp = *(const float2*)(qkv + qbase + 2*lane);
        float qa = qp.x, qb = qp.y;

        float s0 = 0.f, s1 = 0.f, s2 = 0.f;
        #pragma unroll
        for (int k = 0; k < 64; k++) {
            float qv = __shfl_sync(0xffffffffu, (k & 1) ? qb : qa, k >> 1);
            s0 = fmaf(qv, Ks[lane][k],      s0);
            s1 = fmaf(qv, Ks[lane + 32][k], s1);
            s2 = fmaf(qv, Ks[64][k],        s2);
        }
        s0 *= scale; s1 *= scale; s2 *= scale;

        float mx = fmaxf(fmaxf(s0, s1), s2);
        #pragma unroll
        for (int o = 16; o > 0; o >>= 1) mx = fmaxf(mx, __shfl_xor_sync(0xffffffffu, mx, o));
        float e0 = expf(s0 - mx), e1 = expf(s1 - mx), e2 = expf(s2 - mx);
        float ls = e0 + e1;
        #pragma unroll
        for (int o = 16; o > 0; o >>= 1) ls += __shfl_xor_sync(0xffffffffu, ls, o);
        float rinv = 1.0f / (ls + e2);

        Ps[w][lane]      = e0 * rinv;
        Ps[w][lane + 32] = e1 * rinv;
        if (lane == 0) Ps[w][64] = e2 * rinv;
        __syncwarp();

        float o0 = 0.f, o1 = 0.f;
        #pragma unroll 5
        for (int j = 0; j < NP1; j++) {
            float pj = Ps[w][j];
            o0 = fmaf(pj, Vs[j][lane],      o0);
            o1 = fmaf(pj, Vs[j][lane + 32], o1);
        }
        size_t obase = ((size_t)(b*NP1 + qi))*DD + h*DH;
        __nv_bfloat16 h0 = __float2bfloat16_rn(o0), h1 = __float2bfloat16_rn(o1);
        ah[obase + lane]      = h0;
        ah[obase + lane + 32] = h1;
        al[obase + lane]      = __float2bfloat16_rn(o0 - __bfloat162float(h0));
        al[obase + lane + 32] = __float2bfloat16_rn(o1 - __bfloat162float(h1));
        __syncwarp();
    }
}

// ---------------- residual + LayerNorm (in place on xs), emits hi/lo -------
__global__ __launch_bounds__(256)
void ln_res_kernel(const float* __restrict__ add, const float* __restrict__ g,
                   const float* __restrict__ bta, float* __restrict__ xs,
                   __nv_bfloat16* __restrict__ xsh, __nv_bfloat16* __restrict__ xsl)
{
    int row = blockIdx.x, tid = threadIdx.x;
    __shared__ float red[256];
    size_t base = (size_t)row*DD;
    float v0 = xs[base + tid]       + add[base + tid];
    float v1 = xs[base + tid + 256] + add[base + tid + 256];

    red[tid] = v0 + v1; __syncthreads();
    for (int s = 128; s > 0; s >>= 1) { if (tid < s) red[tid] += red[tid+s]; __syncthreads(); }
    float mean = red[0] * (1.0f/(float)DD);
    __syncthreads();
    float d0 = v0 - mean, d1 = v1 - mean;
    red[tid] = d0*d0 + d1*d1; __syncthreads();
    for (int s = 128; s > 0; s >>= 1) { if (tid < s) red[tid] += red[tid+s]; __syncthreads(); }
    float inv = rsqrtf(red[0] * (1.0f/(float)DD) + 1e-5f);

    float y0 = d0*inv*g[tid]       + bta[tid];
    float y1 = d1*inv*g[tid + 256] + bta[tid + 256];
    xs[base + tid] = y0; xs[base + tid + 256] = y1;
    __nv_bfloat16 h0 = __float2bfloat16_rn(y0), h1 = __float2bfloat16_rn(y1);
    xsh[base + tid] = h0;        xsh[base + tid + 256] = h1;
    xsl[base + tid] = __float2bfloat16_rn(y0 - __bfloat162float(h0));
    xsl[base + tid + 256] = __float2bfloat16_rn(y1 - __bfloat162float(h1));
}

// ---------------- MMOT tail: closed-form truncated-geometric softmax -------
__global__ __launch_bounds__(256)
void tail_kernel(const float* __restrict__ hraw, const float* __restrict__ marg,
                 const float* __restrict__ xg, float* __restrict__ hout)
{
    int blk = blockIdx.x;
    int b = blk >> 6, n = blk & 63;
    int tid = threadIdx.x;
    int tok = b*NP1 + n;

    float hr = hraw[(size_t)tok*MM + tid];
    const float DELTA = 6.0f/255.0f;
    float t = hr * (DELTA / 0.01f);
    float q = expf(-fabsf(t));

    float S0 = 1.f, S1 = 0.f, p = q, mcnt = 1.f;
    #pragma unroll
    for (int it = 0; it < 8; it++) {
        S1 = S1 + p*(S1 + mcnt*S0);
        S0 = S0 + p*S0;
        p  = p*p;
        mcnt *= 2.f;
    }
    float f = S1 / S0;
    if (t < 0.f) f = 255.f - f;

    float expected = -3.f + DELTA * f;
    float drift = expected - xg[tid];
    float mu = marg[(size_t)tok*MM + tid];

    __shared__ float r1[256], r2[256];
    r1[tid] = mu * drift; r2[tid] = mu;
    __syncthreads();
    for (int s = 128; s > 0; s >>= 1) {
        if (tid < s) { r1[tid] += r1[tid+s]; r2[tid] += r2[tid+s]; }
        __syncthreads();
    }
    float corr = r1[0] / (r2[0] + 1e-8f);
    hout[(size_t)(b*64 + n)*MM + tid] = hr - corr;
}

// ---------------------------------------------------------------------------
extern "C" void kernel_launch(void* const* d_in, const int* in_sizes, int n_in,
                              void* d_out, int out_size)
{
    const float* marg  = (const float*)d_in[0];
    const float* xg    = (const float*)d_in[1];
    const float* convw = (const float*)d_in[2];
    const float* convb = (const float*)d_in[3];
    const float* fcw   = (const float*)d_in[4];
    const float* fcb   = (const float*)d_in[5];
    const float* ln0g  = (const float*)d_in[6];
    const float* ln0b  = (const float*)d_in[7];
    const float* pos   = (const float*)d_in[8];
    const float* qkvw  = (const float*)d_in[9];
    const float* qkvb  = (const float*)d_in[10];
    const float* outw  = (const float*)d_in[11];
    const float* outb  = (const float*)d_in[12];
    const float* ln1g  = (const float*)d_in[13];
    const float* ln1b  = (const float*)d_in[14];
    const float* ff1w  = (const float*)d_in[15];
    const float* ff1b  = (const float*)d_in[16];
    const float* ff2w  = (const float*)d_in[17];
    const float* ff2b  = (const float*)d_in[18];
    const float* ln2g  = (const float*)d_in[19];
    const float* ln2b  = (const float*)d_in[20];
    const float* uw    = (const float*)d_in[21];
    const float* ub    = (const float*)d_in[22];
    const float* hw    = (const float*)d_in[23];
    const float* hb    = (const float*)d_in[24];

    float *xs, *qkv, *tmp, *hraw;
    __nv_bfloat16 *xsh, *xsl, *ath, *atl, *ffh, *ffl, *wh, *wl;
    cudaGetSymbolAddress((void**)&xs,   g_xs);
    cudaGetSymbolAddress((void**)&xsh,  g_xsh);
    cudaGetSymbolAddress((void**)&xsl,  g_xsl);
    cudaGetSymbolAddress((void**)&qkv,  g_qkv);
    cudaGetSymbolAddress((void**)&ath,  g_ath);
    cudaGetSymbolAddress((void**)&atl,  g_atl);
    cudaGetSymbolAddress((void**)&tmp,  g_tmp);
    cudaGetSymbolAddress((void**)&ffh,  g_ffh);
    cudaGetSymbolAddress((void**)&ffl,  g_ffl);
    cudaGetSymbolAddress((void**)&hraw, g_hraw);
    cudaGetSymbolAddress((void**)&wh,   g_wh);
    cudaGetSymbolAddress((void**)&wl,   g_wl);

    float* out = (float*)d_out;

    const int SM_BIG   = (2*128+2*128)*LDS_B*2;   // 81920
    const int SM_SMALL = (2*64+2*64)*LDS_B*2;     // 40960
    cudaFuncSetAttribute(mma_gemm<0,128,128>, cudaFuncAttributeMaxDynamicSharedMemorySize, SM_BIG);
    cudaFuncSetAttribute(mma_gemm<1,128,128>, cudaFuncAttributeMaxDynamicSharedMemorySize, SM_BIG);
    cudaFuncSetAttribute(mma_gemm<0,64,64>,   cudaFuncAttributeMaxDynamicSharedMemorySize, SM_SMALL);
    cudaFuncSetAttribute(mma_gemm<2,64,64>,   cudaFuncAttributeMaxDynamicSharedMemorySize, SM_SMALL);

    split_all<<<(W_TOT/4 + 255)/256, 256>>>(qkvw, outw, ff1w, ff2w, uw, hw, wh, wl);

    embed_kernel<<<TOK, 256>>>(marg, convw, convb, fcw, fcb, ln0g, ln0b, pos, xs, xsh, xsl);

    const unsigned GY128 = (TOK + 127) / 128;   // 9
    const unsigned GY64  = (TOK + 63) / 64;     // 17
    for (int l = 0; l < LL; l++) {
        mma_gemm<0,128,128><<<dim3(3*DD/128, GY128), 256, SM_BIG>>>(
            xsh, xsl, wh + W_QKV + (size_t)l*3*DD*DD, wl + W_QKV + (size_t)l*3*DD*DD,
            qkvb + l*3*DD, nullptr, qkv, nullptr, nullptr, nullptr, TOK, 3*DD, DD);
        attn_kernel<<<BB*HH, 256>>>(qkv, ath, atl);
        mma_gemm<0,64,64><<<dim3(DD/64, GY64), 128, SM_SMALL>>>(
            ath, atl, wh + W_OUT + (size_t)l*DD*DD, wl + W_OUT + (size_t)l*DD*DD,
            outb + l*DD, nullptr, tmp, nullptr, nullptr, nullptr, TOK, DD, DD);
        ln_res_kernel<<<TOK, 256>>>(tmp, ln1g + l*DD, ln1b + l*DD, xs, xsh, xsl);
        mma_gemm<1,128,128><<<dim3(DFF/128, GY128), 256, SM_BIG>>>(
            xsh, xsl, wh + W_FF1 + (size_t)l*DFF*DD, wl + W_FF1 + (size_t)l*DFF*DD,
            ff1b + l*DFF, nullptr, nullptr, nullptr, ffh, ffl, TOK, DFF, DD);
        mma_gemm<0,64,64><<<dim3(DD/64, GY64), 128, SM_SMALL>>>(
            ffh, ffl, wh + W_FF2 + (size_t)l*DD*DFF, wl + W_FF2 + (size_t)l*DD*DFF,
            ff2b + l*DD, nullptr, tmp, nullptr, nullptr, nullptr, TOK, DD, DFF);
        ln_res_kernel<<<TOK, 256>>>(tmp, ln2g + l*DD, ln2b + l*DD, xs, xsh, xsl);
    }

    // merged u/h GEMM: W rows 0..255 = u_w, 256..511 = h_w (contiguous in arena)
    mma_gemm<2,64,64><<<dim3(512/64, GY64), 128, SM_SMALL>>>(
        xsh, xsl, wh + W_U, wl + W_U, ub, hb, out, hraw, nullptr, nullptr, TOK, 512, DD);

    tail_kernel<<<BB*64, 256>>>(hraw, marg, xg, out + (size_t)TOK*MM);
}

// round 5
// speedup vs baseline: 2.2480x; 1.0181x over previous
#include <cuda_runtime.h>
#include <cuda_bf16.h>
#include <math.h>
#include <stdint.h>

// Problem constants
#define BB    16
#define NP1   65
#define TOK   (BB*NP1)      // 1040
#define MM    256
#define DD    512
#define HH    8
#define DH    64
#define LL    3
#define DFF   2048

// ---------------- weight arena offsets (elements) ---------------------------
#define W_QKV 0
#define W_OUT 2359296
#define W_FF1 3145728
#define W_FF2 6291456
#define W_U   9437184
#define W_H   9568256
#define W_TOT 9699328

// ---------------- scratch (device globals; no allocation allowed) ----------
__device__ __align__(128) float          g_xs  [TOK*DD];
__device__ __align__(128) __nv_bfloat16  g_xsh [TOK*DD];
__device__ __align__(128) __nv_bfloat16  g_xsl [TOK*DD];
__device__ __align__(128) float          g_qkv [TOK*3*DD];
__device__ __align__(128) __nv_bfloat16  g_ath [TOK*DD];
__device__ __align__(128) __nv_bfloat16  g_atl [TOK*DD];
__device__ __align__(128) float          g_tmp [TOK*DD];
__device__ __align__(128) __nv_bfloat16  g_ffh [TOK*DFF];
__device__ __align__(128) __nv_bfloat16  g_ffl [TOK*DFF];
__device__ __align__(128) float          g_hraw[TOK*MM];
__device__ __align__(128) __nv_bfloat16  g_wh  [W_TOT];
__device__ __align__(128) __nv_bfloat16  g_wl  [W_TOT];

// ---------------- PTX helpers (portable to bare sm_103) ---------------------
__device__ __forceinline__ uint32_t s2u(const void* p) {
    uint32_t a;
    asm("{ .reg .u64 t; cvta.to.shared.u64 t, %1; cvt.u32.u64 %0, t; }" : "=r"(a) : "l"(p));
    return a;
}
__device__ __forceinline__ void cp16(uint32_t dst, const void* src) {
    unsigned long long g = (unsigned long long)__cvta_generic_to_global(src);
    asm volatile("cp.async.cg.shared.global [%0], [%1], 16;" :: "r"(dst), "l"(g) : "memory");
}
#define CP_COMMIT() asm volatile("cp.async.commit_group;" ::: "memory")
#define CP_WAIT(n)  asm volatile("cp.async.wait_group %0;" :: "n"(n) : "memory")

__device__ __forceinline__ void ldm4(uint32_t* r, uint32_t a) {
    asm volatile("ldmatrix.sync.aligned.m8n8.x4.shared.b16 {%0,%1,%2,%3}, [%4];"
        : "=r"(r[0]), "=r"(r[1]), "=r"(r[2]), "=r"(r[3]) : "r"(a));
}
__device__ __forceinline__ void mma16816(float* c, const uint32_t* a, uint32_t b0, uint32_t b1) {
    asm volatile("mma.sync.aligned.m16n8k16.row.col.f32.bf16.bf16.f32 "
        "{%0,%1,%2,%3}, {%4,%5,%6,%7}, {%8,%9}, {%0,%1,%2,%3};"
        : "+f"(c[0]), "+f"(c[1]), "+f"(c[2]), "+f"(c[3])
        : "r"(a[0]), "r"(a[1]), "r"(a[2]), "r"(a[3]), "r"(b0), "r"(b1));
}

// ---------------- fused weight split: fp32 arena -> bf16 hi/lo --------------
__global__ __launch_bounds__(256)
void split_all(const float* __restrict__ qkvw, const float* __restrict__ outw,
               const float* __restrict__ ff1w, const float* __restrict__ ff2w,
               const float* __restrict__ uw,   const float* __restrict__ hw,
               __nv_bfloat16* __restrict__ wh, __nv_bfloat16* __restrict__ wl)
{
    size_t i = ((size_t)blockIdx.x*256 + threadIdx.x)*4;
    if (i >= W_TOT) return;
    const float* src;
    if      (i < W_OUT) src = qkvw + i;
    else if (i < W_FF1) src = outw + (i - W_OUT);
    else if (i < W_FF2) src = ff1w + (i - W_FF1);
    else if (i < W_U)   src = ff2w + (i - W_FF2);
    else if (i < W_H)   src = uw   + (i - W_U);
    else                src = hw   + (i - W_H);
    float4 v = *(const float4*)src;
    __nv_bfloat16 h0 = __float2bfloat16_rn(v.x), h1 = __float2bfloat16_rn(v.y);
    __nv_bfloat16 h2 = __float2bfloat16_rn(v.z), h3 = __float2bfloat16_rn(v.w);
    __nv_bfloat162 hp0; hp0.x = h0; hp0.y = h1;
    __nv_bfloat162 hp1; hp1.x = h2; hp1.y = h3;
    ((__nv_bfloat162*)(wh + i))[0] = hp0;
    ((__nv_bfloat162*)(wh + i))[1] = hp1;
    __nv_bfloat162 lp0, lp1;
    lp0.x = __float2bfloat16_rn(v.x - __bfloat162float(h0));
    lp0.y = __float2bfloat16_rn(v.y - __bfloat162float(h1));
    lp1.x = __float2bfloat16_rn(v.z - __bfloat162float(h2));
    lp1.y = __float2bfloat16_rn(v.w - __bfloat162float(h3));
    ((__nv_bfloat162*)(wl + i))[0] = lp0;
    ((__nv_bfloat162*)(wl + i))[1] = lp1;
}

// ---------------- HMMA GEMM: C[m,n] = sum_k A[m,k]*W[n,k] + bias ------------
// Tile BM x BN (BM == BN), warps: 2(M) x BN/32(N), warp tile (BM/2)x32.
// NST-stage cp.async pipeline, K-chunk 32. 3-term split: Ah*Wh + Ah*Wl + Al*Wh.
#define LDS_B 80     // padded row stride (64B payload + 16B pad)

template<int BM, int BN>
__device__ __forceinline__ void load_chunk(uint32_t sb, int stage,
    const __nv_bfloat16* Ah, const __nv_bfloat16* Al,
    const __nv_bfloat16* Wh, const __nv_bfloat16* Wl,
    int m0, int n0, int k0, int M, int K, int tid)
{
    constexpr int AS_LO = BM*LDS_B;
    constexpr int WS_HI = 2*BM*LDS_B;
    constexpr int WS_LO = (2*BM+BN)*LDS_B;
    constexpr int STG   = (2*BM+2*BN)*LDS_B;
    constexpr int NTHR  = 2*BN;
    uint32_t st = sb + stage*STG;
    #pragma unroll
    for (int p = 0; p < 2; p++) {
        int idx = tid + p*NTHR;
        int row = idx >> 2, g = idx & 3;
        int ar = m0 + row; if (ar >= M) ar = M - 1;
        size_t off = (size_t)ar*K + k0 + g*8;
        uint32_t d = row*LDS_B + g*16;
        cp16(st + d,         Ah + off);
        cp16(st + AS_LO + d, Al + off);
    }
    #pragma unroll
    for (int p = 0; p < 2; p++) {
        int idx = tid + p*NTHR;
        int row = idx >> 2, g = idx & 3;
        size_t off = (size_t)(n0 + row)*K + k0 + g*8;
        uint32_t d = row*LDS_B + g*16;
        cp16(st + WS_HI + d, Wh + off);
        cp16(st + WS_LO + d, Wl + off);
    }
}

template<int EPI, int BM, int BN, int NST>
__global__ __launch_bounds__(2*BN, 2)
void mma_gemm(const __nv_bfloat16* __restrict__ Ah, const __nv_bfloat16* __restrict__ Al,
              const __nv_bfloat16* __restrict__ Wh, const __nv_bfloat16* __restrict__ Wl,
              const float* __restrict__ b0, const float* __restrict__ b1,
              float* __restrict__ C0, float* __restrict__ C1,
              __nv_bfloat16* __restrict__ Ch, __nv_bfloat16* __restrict__ Cl,
              int M, int N, int K)
{
    extern __shared__ char smem[];
    constexpr int IT = BM/32;
    constexpr int WN = BN/32;
    constexpr int AS_LO = BM*LDS_B;
    constexpr int WS_HI = 2*BM*LDS_B;
    constexpr int STG   = (2*BM+2*BN)*LDS_B;
    uint32_t sb = s2u(smem);
    int tid = threadIdx.x, wid = tid >> 5, lane = tid & 31;
    int wm = wid / WN, wn = wid % WN;
    int m0 = blockIdx.y * BM, n0 = blockIdx.x * BN;
    const int NC = K >> 5;

    float c[IT][4][4];
    #pragma unroll
    for (int i = 0; i < IT; i++)
        #pragma unroll
        for (int j = 0; j < 4; j++)
            #pragma unroll
            for (int q = 0; q < 4; q++) c[i][j][q] = 0.f;

    #pragma unroll
    for (int s = 0; s < NST; s++) {
        load_chunk<BM,BN>(sb, s, Ah, Al, Wh, Wl, m0, n0, s*32, M, K, tid);
        CP_COMMIT();
    }

    uint32_t lrow = (lane & 15);
    uint32_t koff = (lane >> 4) * 16;

    for (int cc = 0; cc < NC; cc++) {
        CP_WAIT(NST - 1);
        __syncthreads();
        uint32_t st = sb + (cc % NST)*STG;
        #pragma unroll
        for (int ks = 0; ks < 2; ks++) {
            uint32_t kb = ks*32 + koff;
            uint32_t bh[2][4], bl[2][4];
            #pragma unroll
            for (int j2 = 0; j2 < 2; j2++) {
                uint32_t rb = st + WS_HI + (wn*32 + j2*16 + lrow)*LDS_B + kb;
                ldm4(bh[j2], rb);
                ldm4(bl[j2], rb + BN*LDS_B);
            }
            #pragma unroll
            for (int i = 0; i < IT; i++) {
                uint32_t ra = st + (wm*(BM/2) + i*16 + lrow)*LDS_B + kb;
                uint32_t ah[4], al[4];
                ldm4(ah, ra);
                ldm4(al, ra + AS_LO);
                #pragma unroll
                for (int j2 = 0; j2 < 2; j2++) {
                    #pragma unroll
                    for (int jj = 0; jj < 2; jj++) {
                        float* acc = c[i][2*j2 + jj];
                        mma16816(acc, ah, bh[j2][jj], bh[j2][jj+2]);
                        mma16816(acc, ah, bl[j2][jj], bl[j2][jj+2]);
                        mma16816(acc, al, bh[j2][jj], bh[j2][jj+2]);
                    }
                }
            }
        }
        __syncthreads();
        if (cc + NST < NC)
            load_chunk<BM,BN>(sb, cc % NST, Ah, Al, Wh, Wl, m0, n0, (cc+NST)*32, M, K, tid);
        CP_COMMIT();
    }

    // epilogue
    int rbase = m0 + wm*(BM/2) + (lane >> 2);
    int cbase = n0 + wn*32 + 2*(lane & 3);
    #pragma unroll
    for (int i = 0; i < IT; i++) {
        #pragma unroll
        for (int j = 0; j < 4; j++) {
            int col = cbase + j*8;
            float bb0 = b0[col], bb1 = b0[col+1];
            #pragma unroll
            for (int half = 0; half < 2; half++) {
                int r = rbase + i*16 + half*8;
                if (r >= M) continue;
                float v0 = c[i][j][2*half + 0] + bb0;
                float v1 = c[i][j][2*half + 1] + bb1;
                if (EPI == 0) {
                    *(float2*)(C0 + (size_t)r*N + col) = make_float2(v0, v1);
                } else if (EPI == 1) {
                    v0 = 0.5f*v0*(1.0f + erff(v0*0.70710678118654752f));
                    v1 = 0.5f*v1*(1.0f + erff(v1*0.70710678118654752f));
                    __nv_bfloat16 h0 = __float2bfloat16_rn(v0);
                    __nv_bfloat16 h1 = __float2bfloat16_rn(v1);
                    __nv_bfloat162 hp; hp.x = h0; hp.y = h1;
                    __nv_bfloat162 lp;
                    lp.x = __float2bfloat16_rn(v0 - __bfloat162float(h0));
                    lp.y = __float2bfloat16_rn(v1 - __bfloat162float(h1));
                    *(__nv_bfloat162*)(Ch + (size_t)r*N + col) = hp;
                    *(__nv_bfloat162*)(Cl + (size_t)r*N + col) = lp;
                } else {
                    if (col < 256) {
                        *(float2*)(C0 + (size_t)r*256 + col) = make_float2(v0, v1);
                    } else {
                        float u0 = c[i][j][2*half+0] + b1[col-256];
                        float u1 = c[i][j][2*half+1] + b1[col-255];
                        *(float2*)(C1 + (size_t)r*256 + (col-256)) = make_float2(u0, u1);
                    }
                }
            }
        }
    }
}

// ---------------- embed: conv-collapse + fc + LN + GELU + pos --------------
__global__ __launch_bounds__(256)
void embed_kernel(const float* __restrict__ marg, const float* __restrict__ conv_w,
                  const float* __restrict__ conv_b, const float* __restrict__ fc_w,
                  const float* __restrict__ fc_b, const float* __restrict__ ln_g,
                  const float* __restrict__ ln_b, const float* __restrict__ pos,
                  float* __restrict__ xs, __nv_bfloat16* __restrict__ xsh,
                  __nv_bfloat16* __restrict__ xsl)
{
    int row = blockIdx.x;
    int tid = threadIdx.x;
    __shared__ float red[256];
    __shared__ float e[128];

    const float* x = marg + (size_t)row * MM;
    red[tid] = x[tid];
    __syncthreads();
    for (int s = 128; s > 0; s >>= 1) { if (tid < s) red[tid] += red[tid+s]; __syncthreads(); }
    float S = red[0];
    __syncthreads();

    if (tid < 128) {
        float x0 = x[0], x1 = x[1], xm2 = x[MM-2], xm1 = x[MM-1];
        const float* w = conv_w + tid*5;
        float acc = w[0]*(S - xm2 - xm1) + w[1]*(S - xm1) + w[2]*S
                  + w[3]*(S - x0)        + w[4]*(S - x0 - x1);
        e[tid] = conv_b[tid] + acc * (1.0f/(float)MM);
    }
    __syncthreads();

    float t0 = fc_b[tid], t1 = fc_b[tid+256];
    #pragma unroll 4
    for (int c = 0; c < 128; c++) {
        float ec = e[c];
        t0 += ec * fc_w[c*DD + tid];
        t1 += ec * fc_w[c*DD + tid + 256];
    }

    red[tid] = t0 + t1; __syncthreads();
    for (int s = 128; s > 0; s >>= 1) { if (tid < s) red[tid] += red[tid+s]; __syncthreads(); }
    float mean = red[0] * (1.0f/(float)DD);
    __syncthreads();
    float d0 = t0 - mean, d1 = t1 - mean;
    red[tid] = d0*d0 + d1*d1; __syncthreads();
    for (int s = 128; s > 0; s >>= 1) { if (tid < s) red[tid] += red[tid+s]; __syncthreads(); }
    float inv = rsqrtf(red[0] * (1.0f/(float)DD) + 1e-5f);

    float y0 = d0*inv*ln_g[tid]     + ln_b[tid];
    float y1 = d1*inv*ln_g[tid+256] + ln_b[tid+256];
    y0 = 0.5f*y0*(1.0f + erff(y0*0.70710678118654752f));
    y1 = 0.5f*y1*(1.0f + erff(y1*0.70710678118654752f));

    int p = row % NP1;
    float v0 = y0 + pos[p*DD + tid];
    float v1 = y1 + pos[p*DD + tid + 256];
    size_t base = (size_t)row*DD;
    xs[base + tid] = v0; xs[base + tid + 256] = v1;
    __nv_bfloat16 h0 = __float2bfloat16_rn(v0), h1 = __float2bfloat16_rn(v1);
    xsh[base + tid] = h0;        xsh[base + tid + 256] = h1;
    xsl[base + tid] = __float2bfloat16_rn(v0 - __bfloat162float(h0));
    xsl[base + tid + 256] = __float2bfloat16_rn(v1 - __bfloat162float(h1));
}

// ---------------- attention: one block per (b,h), 16 warps -----------------
__global__ __launch_bounds__(512)
void attn_kernel(const float* __restrict__ qkv, __nv_bfloat16* __restrict__ ah,
                 __nv_bfloat16* __restrict__ al)
{
    int bh = blockIdx.x;
    int b = bh >> 3, h = bh & 7;
    __shared__ float Ks[NP1][65];   // pitch 65: conflict-free row reads across lanes
    __shared__ float Vs[NP1][64];
    __shared__ float Ps[16][72];

    int tid = threadIdx.x, lane = tid & 31, w = tid >> 5;   // w: 0..15

    for (int idx = tid; idx < NP1*64; idx += 512) {
        int j = idx >> 6, k = idx & 63;
        size_t base = ((size_t)(b*NP1 + j))*(3*DD) + h*DH + k;
        Ks[j][k] = qkv[base + DD];
        Vs[j][k] = qkv[base + 2*DD];
    }
    __syncthreads();

    const float scale = 0.125f;
    for (int qi = w; qi < NP1; qi += 16) {
        size_t qbase = ((size_t)(b*NP1 + qi))*(3*DD) + h*DH;
        float2 qp = *(const float2*)(qkv + qbase + 2*lane);
        float qa = qp.x, qb = qp.y;

        float s0 = 0.f, s1 = 0.f, s2 = 0.f;
        #pragma unroll
        for (int k = 0; k < 64; k++) {
            float qv = __shfl_sync(0xffffffffu, (k & 1) ? qb : qa, k >> 1);
            s0 = fmaf(qv, Ks[lane][k],      s0);
            s1 = fmaf(qv, Ks[lane + 32][k], s1);
            s2 = fmaf(qv, Ks[64][k],        s2);
        }
        s0 *= scale; s1 *= scale; s2 *= scale;

        float mx = fmaxf(fmaxf(s0, s1), s2);
        #pragma unroll
        for (int o = 16; o > 0; o >>= 1) mx = fmaxf(mx, __shfl_xor_sync(0xffffffffu, mx, o));
        float e0 = expf(s0 - mx), e1 = expf(s1 - mx), e2 = expf(s2 - mx);
        float ls = e0 + e1;
        #pragma unroll
        for (int o = 16; o > 0; o >>= 1) ls += __shfl_xor_sync(0xffffffffu, ls, o);
        float rinv = 1.0f / (ls + e2);

        Ps[w][lane]      = e0 * rinv;
        Ps[w][lane + 32] = e1 * rinv;
        if (lane == 0) Ps[w][64] = e2 * rinv;
        __syncwarp();

        float o0 = 0.f, o1 = 0.f;
        #pragma unroll 5
        for (int j = 0; j < NP1; j++) {
            float pj = Ps[w][j];
            o0 = fmaf(pj, Vs[j][lane],      o0);
            o1 = fmaf(pj, Vs[j][lane + 32], o1);
        }
        size_t obase = ((size_t)(b*NP1 + qi))*DD + h*DH;
        __nv_bfloat16 h0 = __float2bfloat16_rn(o0), h1 = __float2bfloat16_rn(o1);
        ah[obase + lane]      = h0;
        ah[obase + lane + 32] = h1;
        al[obase + lane]      = __float2bfloat16_rn(o0 - __bfloat162float(h0));
        al[obase + lane + 32] = __float2bfloat16_rn(o1 - __bfloat162float(h1));
        __syncwarp();
    }
}

// ---------------- residual + LayerNorm (in place on xs), emits hi/lo -------
__global__ __launch_bounds__(256)
void ln_res_kernel(const float* __restrict__ add, const float* __restrict__ g,
                   const float* __restrict__ bta, float* __restrict__ xs,
                   __nv_bfloat16* __restrict__ xsh, __nv_bfloat16* __restrict__ xsl)
{
    int row = blockIdx.x, tid = threadIdx.x;
    __shared__ float red[256];
    size_t base = (size_t)row*DD;
    float v0 = xs[base + tid]       + add[base + tid];
    float v1 = xs[base + tid + 256] + add[base + tid + 256];

    red[tid] = v0 + v1; __syncthreads();
    for (int s = 128; s > 0; s >>= 1) { if (tid < s) red[tid] += red[tid+s]; __syncthreads(); }
    float mean = red[0] * (1.0f/(float)DD);
    __syncthreads();
    float d0 = v0 - mean, d1 = v1 - mean;
    red[tid] = d0*d0 + d1*d1; __syncthreads();
    for (int s = 128; s > 0; s >>= 1) { if (tid < s) red[tid] += red[tid+s]; __syncthreads(); }
    float inv = rsqrtf(red[0] * (1.0f/(float)DD) + 1e-5f);

    float y0 = d0*inv*g[tid]       + bta[tid];
    float y1 = d1*inv*g[tid + 256] + bta[tid + 256];
    xs[base + tid] = y0; xs[base + tid + 256] = y1;
    __nv_bfloat16 h0 = __float2bfloat16_rn(y0), h1 = __float2bfloat16_rn(y1);
    xsh[base + tid] = h0;        xsh[base + tid + 256] = h1;
    xsl[base + tid] = __float2bfloat16_rn(y0 - __bfloat162float(h0));
    xsl[base + tid + 256] = __float2bfloat16_rn(y1 - __bfloat162float(h1));
}

// ---------------- MMOT tail: closed-form truncated-geometric softmax -------
__global__ __launch_bounds__(256)
void tail_kernel(const float* __restrict__ hraw, const float* __restrict__ marg,
                 const float* __restrict__ xg, float* __restrict__ hout)
{
    int blk = blockIdx.x;
    int b = blk >> 6, n = blk & 63;
    int tid = threadIdx.x;
    int tok = b*NP1 + n;

    float hr = hraw[(size_t)tok*MM + tid];
    const float DELTA = 6.0f/255.0f;
    float t = hr * (DELTA / 0.01f);
    float q = expf(-fabsf(t));

    float S0 = 1.f, S1 = 0.f, p = q, mcnt = 1.f;
    #pragma unroll
    for (int it = 0; it < 8; it++) {
        S1 = S1 + p*(S1 + mcnt*S0);
        S0 = S0 + p*S0;
        p  = p*p;
        mcnt *= 2.f;
    }
    float f = S1 / S0;
    if (t < 0.f) f = 255.f - f;

    float expected = -3.f + DELTA * f;
    float drift = expected - xg[tid];
    float mu = marg[(size_t)tok*MM + tid];

    __shared__ float r1[256], r2[256];
    r1[tid] = mu * drift; r2[tid] = mu;
    __syncthreads();
    for (int s = 128; s > 0; s >>= 1) {
        if (tid < s) { r1[tid] += r1[tid+s]; r2[tid] += r2[tid+s]; }
        __syncthreads();
    }
    float corr = r1[0] / (r2[0] + 1e-8f);
    hout[(size_t)(b*64 + n)*MM + tid] = hr - corr;
}

// ---------------------------------------------------------------------------
extern "C" void kernel_launch(void* const* d_in, const int* in_sizes, int n_in,
                              void* d_out, int out_size)
{
    const float* marg  = (const float*)d_in[0];
    const float* xg    = (const float*)d_in[1];
    const float* convw = (const float*)d_in[2];
    const float* convb = (const float*)d_in[3];
    const float* fcw   = (const float*)d_in[4];
    const float* fcb   = (const float*)d_in[5];
    const float* ln0g  = (const float*)d_in[6];
    const float* ln0b  = (const float*)d_in[7];
    const float* pos   = (const float*)d_in[8];
    const float* qkvw  = (const float*)d_in[9];
    const float* qkvb  = (const float*)d_in[10];
    const float* outw  = (const float*)d_in[11];
    const float* outb  = (const float*)d_in[12];
    const float* ln1g  = (const float*)d_in[13];
    const float* ln1b  = (const float*)d_in[14];
    const float* ff1w  = (const float*)d_in[15];
    const float* ff1b  = (const float*)d_in[16];
    const float* ff2w  = (const float*)d_in[17];
    const float* ff2b  = (const float*)d_in[18];
    const float* ln2g  = (const float*)d_in[19];
    const float* ln2b  = (const float*)d_in[20];
    const float* uw    = (const float*)d_in[21];
    const float* ub    = (const float*)d_in[22];
    const float* hw    = (const float*)d_in[23];
    const float* hb    = (const float*)d_in[24];

    float *xs, *qkv, *tmp, *hraw;
    __nv_bfloat16 *xsh, *xsl, *ath, *atl, *ffh, *ffl, *wh, *wl;
    cudaGetSymbolAddress((void**)&xs,   g_xs);
    cudaGetSymbolAddress((void**)&xsh,  g_xsh);
    cudaGetSymbolAddress((void**)&xsl,  g_xsl);
    cudaGetSymbolAddress((void**)&qkv,  g_qkv);
    cudaGetSymbolAddress((void**)&ath,  g_ath);
    cudaGetSymbolAddress((void**)&atl,  g_atl);
    cudaGetSymbolAddress((void**)&tmp,  g_tmp);
    cudaGetSymbolAddress((void**)&ffh,  g_ffh);
    cudaGetSymbolAddress((void**)&ffl,  g_ffl);
    cudaGetSymbolAddress((void**)&hraw, g_hraw);
    cudaGetSymbolAddress((void**)&wh,   g_wh);
    cudaGetSymbolAddress((void**)&wl,   g_wl);

    float* out = (float*)d_out;

    const int SM_BIG   = (2*128+2*128)*LDS_B*2;   // 81920 (2 stages)
    const int SM_SMALL = (2*64+2*64)*LDS_B*3;     // 61440 (3 stages)
    cudaFuncSetAttribute(mma_gemm<0,128,128,2>, cudaFuncAttributeMaxDynamicSharedMemorySize, SM_BIG);
    cudaFuncSetAttribute(mma_gemm<1,128,128,2>, cudaFuncAttributeMaxDynamicSharedMemorySize, SM_BIG);
    cudaFuncSetAttribute(mma_gemm<0,64,64,3>,   cudaFuncAttributeMaxDynamicSharedMemorySize, SM_SMALL);
    cudaFuncSetAttribute(mma_gemm<2,64,64,3>,   cudaFuncAttributeMaxDynamicSharedMemorySize, SM_SMALL);

    split_all<<<(W_TOT/4 + 255)/256, 256>>>(qkvw, outw, ff1w, ff2w, uw, hw, wh, wl);

    embed_kernel<<<TOK, 256>>>(marg, convw, convb, fcw, fcb, ln0g, ln0b, pos, xs, xsh, xsl);

    const unsigned GY128 = (TOK + 127) / 128;   // 9
    const unsigned GY64  = (TOK + 63) / 64;     // 17
    for (int l = 0; l < LL; l++) {
        mma_gemm<0,128,128,2><<<dim3(3*DD/128, GY128), 256, SM_BIG>>>(
            xsh, xsl, wh + W_QKV + (size_t)l*3*DD*DD, wl + W_QKV + (size_t)l*3*DD*DD,
            qkvb + l*3*DD, nullptr, qkv, nullptr, nullptr, nullptr, TOK, 3*DD, DD);
        attn_kernel<<<BB*HH, 512>>>(qkv, ath, atl);
        mma_gemm<0,64,64,3><<<dim3(DD/64, GY64), 128, SM_SMALL>>>(
            ath, atl, wh + W_OUT + (size_t)l*DD*DD, wl + W_OUT + (size_t)l*DD*DD,
            outb + l*DD, nullptr, tmp, nullptr, nullptr, nullptr, TOK, DD, DD);
        ln_res_kernel<<<TOK, 256>>>(tmp, ln1g + l*DD, ln1b + l*DD, xs, xsh, xsl);
        mma_gemm<1,128,128,2><<<dim3(DFF/128, GY128), 256, SM_BIG>>>(
            xsh, xsl, wh + W_FF1 + (size_t)l*DFF*DD, wl + W_FF1 + (size_t)l*DFF*DD,
            ff1b + l*DFF, nullptr, nullptr, nullptr, ffh, ffl, TOK, DFF, DD);
        mma_gemm<0,64,64,3><<<dim3(DD/64, GY64), 128, SM_SMALL>>>(
            ffh, ffl, wh + W_FF2 + (size_t)l*DD*DFF, wl + W_FF2 + (size_t)l*DD*DFF,
            ff2b + l*DD, nullptr, tmp, nullptr, nullptr, nullptr, TOK, DD, DFF);
        ln_res_kernel<<<TOK, 256>>>(tmp, ln2g + l*DD, ln2b + l*DD, xs, xsh, xsl);
    }

    // merged u/h GEMM: W rows 0..255 = u_w, 256..511 = h_w (contiguous in arena)
    mma_gemm<2,64,64,3><<<dim3(512/64, GY64), 128, SM_SMALL>>>(
        xsh, xsl, wh + W_U, wl + W_U, ub, hb, out, hraw, nullptr, nullptr, TOK, 512, DD);

    tail_kernel<<<BB*64, 256>>>(hraw, marg, xg, out + (size_t)TOK*MM);
}